// round 16
// baseline (speedup 1.0000x reference)
#include <cuda_runtime.h>
#include <cuda_fp16.h>
#include <math.h>
#include <stdint.h>

// Problem geometry (fixed by the dataset)
#define N0c 1048576
#define N1c 65536
#define N2c 4096
#define DEG0c 16
#define DEG1c 10
#define DINc 128
#define DHc 256
#define DOUTc 47
#define E1c (N2c * DEG1c)

// Scratch (alloc-free: __device__ globals)
__device__ __half  g_A0[(size_t)N1c * 256];    // 32 MB  [mean|self] fp16, layer0
__device__ __half  g_h0[(size_t)N1c * 256];    // 32 MB  h0 fp16 (compact rows)
__device__ __half  g_W0[256 * 256];            // [Wl0|Wr0] fp16
__device__ __half  g_W1[256 * 512];            // [Wl1|Wr1] fp16
__device__ __half  g_Wo2[48 * 256];            // Wo fp16, zero-padded to 48 rows
__device__ int     g_list [N1c];               // compact row -> node id
__device__ int     g_remap[N1c];               // node id -> compact row (-1 = unused)
__device__ int     g_cnt;
__device__ int     g_mbflag[1024];             // per-m-block A0-ready flags

__device__ __forceinline__ float gelu_exact(float v) {
    return 0.5f * v * (1.0f + erff(v * 0.7071067811865476f));
}

__device__ __forceinline__ void cp16(uint32_t saddr, const void* gaddr) {
    asm volatile("cp.async.cg.shared.global [%0], [%1], 16;\n" :: "r"(saddr), "l"(gaddr));
}

// ---------------------------------------------------------------------------
// prep: remap/list/cnt/flag init + fp16 weight conversion, one launch.
// ---------------------------------------------------------------------------
__global__ void prep_kernel(const float* __restrict__ Wl0, const float* __restrict__ Wr0,
                            const float* __restrict__ Wl1, const float* __restrict__ Wr1,
                            const float* __restrict__ Wo,
                            __half* __restrict__ W0, __half* __restrict__ W1,
                            __half* __restrict__ Wo2,
                            int* __restrict__ list, int* __restrict__ remap,
                            int* __restrict__ cnt, int* __restrict__ mbflag)
{
    const int t = blockIdx.x * blockDim.x + threadIdx.x;
    if (t < N1c) {
        remap[t] = (t < N2c) ? t : -1;     // seeds claim slots 0..4095
        list[t]  = (t < N2c) ? t : 0;      // padding rows alias node 0
    }
    if (t < 1024) mbflag[t] = 0;
    if (t == 0) *cnt = N2c;
    if (t < 65536) {                       // W0: 256 x 256
        const int n = t >> 8, k = t & 255;
        W0[t] = __float2half_rn(k < 128 ? Wl0[n * 128 + k] : Wr0[n * 128 + (k - 128)]);
    }
    const int t1 = t - 65536;              // W1: 256 x 512
    if (t1 >= 0 && t1 < 131072) {
        const int n = t1 >> 9, k = t1 & 511;
        W1[t1] = __float2half_rn(k < 256 ? Wl1[n * 256 + k] : Wr1[n * 256 + (k - 256)]);
    }
    const int t2 = t - 196608;             // Wo2: 48 x 256 (rows >=47 zero)
    if (t2 >= 0 && t2 < 48 * 256) {
        const int n = t2 >> 8, k = t2 & 255;
        Wo2[t2] = (n < DOUTc) ? __float2half_rn(Wo[n * 256 + k]) : __float2half_rn(0.f);
    }
}

// ---------------------------------------------------------------------------
// claim: per-edge CAS dedup.
// ---------------------------------------------------------------------------
__global__ void claim_kernel(const int* __restrict__ idx1, int* list,
                             int* remap, int* cnt)
{
    const int t = blockIdx.x * blockDim.x + threadIdx.x;
    if (t >= E1c) return;
    const int src = idx1[t];
    if (remap[src] == -1) {
        if (atomicCAS(&remap[src], -1, -2) == -1) {
            const int p = atomicAdd(cnt, 1);
            list[p] = src;
            remap[src] = p;
        }
    }
}

// ---------------------------------------------------------------------------
// FUSED layer 0, two sequential phases per CTA (grid 444 = 3 CTAs/SM, all
// resident -> flag waits deadlock-free):
//   Phase 1: EVERY CTA gathers its mbs (full-chip, HBM-bound), builds
//            A0[mb] = [fp16(mean16(x))|fp16(x_self)], flags each mb.
//   Phase 2: CTA owns W0 quarter (bid&3) resident in smem; polls flags and
//            runs 64x64x256 m16n8k16 GEMM per mb -> h0 = gelu(A@Wq^T+b).
// GEMM work of early-finishing CTAs overlaps the gather of stragglers.
// ---------------------------------------------------------------------------
__global__ void __launch_bounds__(256, 3)
sage_l0(const float* __restrict__ x, const int* __restrict__ idx0,
        const int* __restrict__ list, const int* __restrict__ cntp,
        __half* __restrict__ A0, const __half* __restrict__ W0,
        const float* __restrict__ bias, __half* __restrict__ h0,
        int* __restrict__ mbflag)
{
    extern __shared__ char smraw[];
    const int tid  = threadIdx.x;
    const int lane = tid & 31;
    const int warp = tid >> 5;
    const int cnt  = *cntp;
    const int n_mb = (cnt + 63) >> 6;

    // ================= Phase 1: GATHER (all CTAs) =================
    {
        float4* sbuf = (float4*)smraw;              // [2][4*17*32] = 69632 B
        const uint32_t sbase = (uint32_t)__cvta_generic_to_shared(sbuf);

        auto stage = [&](int mb, int s, int buf) {
            #pragma unroll
            for (int p = 0; p < 9; p++) {
                const int c = tid + p * 256;
                if (c < 2176) {                     // 4 dst * 17 rows * 32 chunks
                    const int eg = c >> 5, col = c & 31;
                    const int dl = eg / 17, e = eg % 17;
                    const int node = list[mb * 64 + s * 4 + dl];
                    const int src = (e < 16) ? idx0[(size_t)node * 16 + e] : node;
                    cp16(sbase + (uint32_t)(buf * 2176 + c) * 16u,
                         x + (size_t)src * 128 + col * 4);
                }
            }
            asm volatile("cp.async.commit_group;\n" ::);
        };

        for (int mb = blockIdx.x; mb < n_mb; mb += 444) {
            stage(mb, 0, 0);
            #pragma unroll 1
            for (int s = 0; s < 16; s++) {
                if (s < 15) {
                    stage(mb, s + 1, (s + 1) & 1);
                    asm volatile("cp.async.wait_group 1;\n" ::);
                } else {
                    asm volatile("cp.async.wait_group 0;\n" ::);
                }
                __syncthreads();
                if (tid < 128) {                    // reduce 4 dst x 32 f4-cols
                    const int dl = tid >> 5, col = tid & 31;
                    const float4* base = sbuf + (size_t)(s & 1) * 2176 + dl * 17 * 32;
                    float4 acc = make_float4(0.f, 0.f, 0.f, 0.f);
                    #pragma unroll
                    for (int e = 0; e < 16; e++) {
                        float4 v = base[e * 32 + col];
                        acc.x += v.x; acc.y += v.y; acc.z += v.z; acc.w += v.w;
                    }
                    const float4 self = base[16 * 32 + col];
                    const float inv = 1.0f / 16.0f;
                    const int row = mb * 64 + s * 4 + dl;
                    __half2* rowm = (__half2*)(A0 + (size_t)row * 256);
                    rowm[col * 2]     = __floats2half2_rn(acc.x * inv, acc.y * inv);
                    rowm[col * 2 + 1] = __floats2half2_rn(acc.z * inv, acc.w * inv);
                    __half2* rows = rowm + 64;
                    rows[col * 2]     = __floats2half2_rn(self.x, self.y);
                    rows[col * 2 + 1] = __floats2half2_rn(self.z, self.w);
                }
                __syncthreads();
            }
            __threadfence();
            if (tid == 0) atomicExch(&mbflag[mb], 1);
        }
    }
    __syncthreads();   // gather buffer dead; reuse smem for GEMM

    // ================= Phase 2: GEMM (same CTAs) =================
    constexpr int WP = 264, AP = 264;               // smem pitches (halves)
    __half* Ws = (__half*)smraw;                    // [64][WP] = 33792 B
    __half* As = (__half*)smraw + 64 * WP;          // [64][AP] = 33792 B
    const uint32_t sW = (uint32_t)__cvta_generic_to_shared(Ws);
    const uint32_t sA = (uint32_t)__cvta_generic_to_shared(As);

    const int quarter = blockIdx.x & 3;
    const int q0      = blockIdx.x >> 2;            // 0..110
    const int n0      = quarter * 64;

    // Load W quarter once: 64 rows x 256 halves = 2048 16B chunks
    #pragma unroll
    for (int i = 0; i < 8; i++) {
        const int c = tid + i * 256;
        const int r = c >> 5, k16 = c & 31;
        cp16(sW + (uint32_t)(r * WP + k16 * 8) * 2u,
             W0 + (size_t)(n0 + r) * 256 + k16 * 8);
    }
    asm volatile("cp.async.commit_group;\n" ::);

    const int quad = lane >> 3, qr = lane & 7;
    const int warpM = warp & 1;                     // 2 x 32 rows
    const int warpN = warp >> 1;                    // 4 x 16 cols
    const int aRowB = warpM * 32 + (quad & 1) * 8 + qr;   // + mi*16
    const int aColH = (quad >> 1) * 8;
    const int bRow4 = warpN * 16 + (lane & 7) + ((lane >> 4) & 1) * 8;
    const int bCol4 = ((lane >> 3) & 1) * 8;
    const int g = lane >> 2, l = lane & 3;

    #pragma unroll 1
    for (int mb = q0; mb < n_mb; mb += 111) {
        if (tid == 0) {
            while (atomicAdd(&mbflag[mb], 0) == 0) __nanosleep(64);
        }
        __syncthreads();

        // Fetch A0 tile: 64 rows x 256 halves = 2048 16B chunks
        #pragma unroll
        for (int i = 0; i < 8; i++) {
            const int c = tid + i * 256;
            const int r = c >> 5, k16 = c & 31;
            cp16(sA + (uint32_t)(r * AP + k16 * 8) * 2u,
                 A0 + (size_t)(mb * 64 + r) * 256 + k16 * 8);
        }
        asm volatile("cp.async.commit_group;\n" ::);
        asm volatile("cp.async.wait_group 0;\n" ::);
        __syncthreads();

        float acc[2][2][4] = {};
        #pragma unroll
        for (int ks = 0; ks < 16; ks++) {
            uint32_t a[2][4], b[2][2];
            #pragma unroll
            for (int mi = 0; mi < 2; mi++) {
                uint32_t ad = sA + (uint32_t)(((aRowB + mi * 16) * AP) + ks * 16 + aColH) * 2u;
                asm volatile("ldmatrix.sync.aligned.m8n8.x4.shared.b16 {%0,%1,%2,%3}, [%4];\n"
                             : "=r"(a[mi][0]), "=r"(a[mi][1]), "=r"(a[mi][2]), "=r"(a[mi][3])
                             : "r"(ad));
            }
            {
                uint32_t bd = sW + (uint32_t)((bRow4 * WP) + ks * 16 + bCol4) * 2u;
                asm volatile("ldmatrix.sync.aligned.m8n8.x4.shared.b16 {%0,%1,%2,%3}, [%4];\n"
                             : "=r"(b[0][0]), "=r"(b[0][1]), "=r"(b[1][0]), "=r"(b[1][1])
                             : "r"(bd));
            }
            #pragma unroll
            for (int mi = 0; mi < 2; mi++)
                #pragma unroll
                for (int ni = 0; ni < 2; ni++)
                    asm volatile(
                        "mma.sync.aligned.m16n8k16.row.col.f32.f16.f16.f32 "
                        "{%0,%1,%2,%3}, {%4,%5,%6,%7}, {%8,%9}, {%0,%1,%2,%3};\n"
                        : "+f"(acc[mi][ni][0]), "+f"(acc[mi][ni][1]),
                          "+f"(acc[mi][ni][2]), "+f"(acc[mi][ni][3])
                        : "r"(a[mi][0]), "r"(a[mi][1]), "r"(a[mi][2]), "r"(a[mi][3]),
                          "r"(b[ni][0]), "r"(b[ni][1]));
        }
        __syncthreads();   // all warps done reading As before next fetch

        #pragma unroll
        for (int mi = 0; mi < 2; mi++)
            #pragma unroll
            for (int ni = 0; ni < 2; ni++) {
                const int m = mb * 64 + warpM * 32 + mi * 16 + g;
                const int n = n0 + warpN * 16 + ni * 8 + 2 * l;
                float* c = acc[mi][ni];
                *(__half2*)&h0[(size_t)m * 256 + n] =
                    __floats2half2_rn(gelu_exact(c[0] + bias[n]), gelu_exact(c[1] + bias[n + 1]));
                *(__half2*)&h0[(size_t)(m + 8) * 256 + n] =
                    __floats2half2_rn(gelu_exact(c[2] + bias[n]), gelu_exact(c[3] + bias[n + 1]));
            }
    }
}

// ---------------------------------------------------------------------------
// Layer-1 GEMM with INTEGRATED aggregation + fused 47-wide projection.
// (R14/R15 configuration — protected)
// ---------------------------------------------------------------------------
__global__ void __launch_bounds__(256)
gemm1_fused(const __half* __restrict__ h0, const int* __restrict__ idx1,
            const int* __restrict__ srcmap,
            const __half* __restrict__ W, const float* __restrict__ bias,
            float* __restrict__ C,
            const __half* __restrict__ Wo2, const float* __restrict__ bo)
{
    constexpr int KTOT = 512;
    constexpr int SA = 72;
    constexpr int AP = 520;
    constexpr int AW = 32 * AP;
    constexpr int WW = 256 * SA;

    const int m0 = blockIdx.x * 32;

    extern __shared__ __half sm[];
    __half* As = sm;
    __half* Ws = sm + AW;

    const int tid  = threadIdx.x;
    const int lane = tid & 31;
    const int warp = tid >> 5;
    const int warpM = warp & 1;
    const int warpN = warp >> 1;
    const int arow8 = tid >> 3;
    const int lcolh = (tid & 7) * 8;

    const uint32_t sA = (uint32_t)__cvta_generic_to_shared(As);
    const uint32_t sW = (uint32_t)__cvta_generic_to_shared(Ws);

    auto fetchW = [&](int it, int buf) {
        const int gk = it * 64 + lcolh;
        #pragma unroll
        for (int p = 0; p < 8; p++) {
            const int nr = arow8 + p * 32;
            cp16(sW + (uint32_t)(buf * WW + nr * SA + lcolh) * 2u,
                 W + (size_t)nr * KTOT + gk);
        }
    };

    fetchW(0, 0);
    asm volatile("cp.async.commit_group;\n" ::);

    // integrated aggregation: build A rows in smem
    {
        const float inv = 1.0f / (float)DEG1c;
        #pragma unroll 1
        for (int dl = 0; dl < 4; dl++) {
            const int row = warp * 4 + dl;
            const int dst = m0 + row;
            float accf[8] = {};
            #pragma unroll
            for (int e = 0; e < DEG1c; e++) {
                const int src = srcmap[idx1[dst * DEG1c + e]];
                const uint4 v = *(const uint4*)(h0 + (size_t)src * 256 + lane * 8);
                const __half2* hp = (const __half2*)&v;
                #pragma unroll
                for (int j = 0; j < 4; j++) {
                    float2 f = __half22float2(hp[j]);
                    accf[j * 2] += f.x; accf[j * 2 + 1] += f.y;
                }
            }
            const uint4 sv = *(const uint4*)(h0 + (size_t)dst * 256 + lane * 8);
            __half* arow = As + row * AP;
            __half2* mo = (__half2*)(arow + lane * 8);
            mo[0] = __floats2half2_rn(accf[0] * inv, accf[1] * inv);
            mo[1] = __floats2half2_rn(accf[2] * inv, accf[3] * inv);
            mo[2] = __floats2half2_rn(accf[4] * inv, accf[5] * inv);
            mo[3] = __floats2half2_rn(accf[6] * inv, accf[7] * inv);
            *(uint4*)(arow + 256 + lane * 8) = sv;
        }
    }
    __syncthreads();

    float acc[8][4] = {};

    const int quad = lane >> 3, qr = lane & 7;
    const int aRowB = warpM * 16 + (quad & 1) * 8 + qr;
    const int aColH = (quad >> 1) * 8;
    const int bRow4 = warpN * 64 + (lane & 7) + ((lane >> 4) & 1) * 8;
    const int bCol4 = ((lane >> 3) & 1) * 8;

    constexpr int nk = KTOT / 64;
    int buf = 0;
    #pragma unroll 1
    for (int it = 0; it < nk; it++) {
        if (it + 1 < nk) {
            fetchW(it + 1, buf ^ 1);
            asm volatile("cp.async.commit_group;\n" ::);
            asm volatile("cp.async.wait_group 1;\n" ::);
        } else {
            asm volatile("cp.async.wait_group 0;\n" ::);
        }
        __syncthreads();

        const uint32_t baseW = sW + (uint32_t)(buf * WW) * 2u;

        #pragma unroll
        for (int ks = 0; ks < 4; ks++) {
            uint32_t a[4], b[8][2];
            uint32_t ad = sA + (uint32_t)((aRowB * AP) + it * 64 + ks * 16 + aColH) * 2u;
            asm volatile("ldmatrix.sync.aligned.m8n8.x4.shared.b16 {%0,%1,%2,%3}, [%4];\n"
                         : "=r"(a[0]), "=r"(a[1]), "=r"(a[2]), "=r"(a[3]) : "r"(ad));
            #pragma unroll
            for (int ni2 = 0; ni2 < 4; ni2++) {
                uint32_t bd = baseW + (uint32_t)(((bRow4 + ni2 * 16) * SA) + ks * 16 + bCol4) * 2u;
                asm volatile("ldmatrix.sync.aligned.m8n8.x4.shared.b16 {%0,%1,%2,%3}, [%4];\n"
                             : "=r"(b[ni2 * 2][0]), "=r"(b[ni2 * 2][1]),
                               "=r"(b[ni2 * 2 + 1][0]), "=r"(b[ni2 * 2 + 1][1])
                             : "r"(bd));
            }
            #pragma unroll
            for (int ni = 0; ni < 8; ni++)
                asm volatile(
                    "mma.sync.aligned.m16n8k16.row.col.f32.f16.f16.f32 "
                    "{%0,%1,%2,%3}, {%4,%5,%6,%7}, {%8,%9}, {%0,%1,%2,%3};\n"
                    : "+f"(acc[ni][0]), "+f"(acc[ni][1]),
                      "+f"(acc[ni][2]), "+f"(acc[ni][3])
                    : "r"(a[0]), "r"(a[1]), "r"(a[2]), "r"(a[3]),
                      "r"(b[ni][0]), "r"(b[ni][1]));
        }
        __syncthreads();
        buf ^= 1;
    }

    const int g = lane >> 2, l = lane & 3;

    constexpr int HP = 264;
    __half* h1t = Ws;
    __half* WoS = As;

    __syncthreads();
    #pragma unroll
    for (int ni = 0; ni < 8; ni++) {
        const int ml = warpM * 16 + g;
        const int n  = warpN * 64 + ni * 8 + 2 * l;
        float* c = acc[ni];
        *(__half2*)&h1t[ml * HP + n] =
            __floats2half2_rn(gelu_exact(c[0] + bias[n]), gelu_exact(c[1] + bias[n + 1]));
        *(__half2*)&h1t[(ml + 8) * HP + n] =
            __floats2half2_rn(gelu_exact(c[2] + bias[n]), gelu_exact(c[3] + bias[n + 1]));
    }
    __syncthreads();

    const int warpM2 = warp & 1;
    const int warpN2 = warp >> 1;
    const int aRow2 = warpM2 * 16 + (quad & 1) * 8 + qr;
    const int bRow4p = warpN2 * 16 + (lane & 7) + ((lane >> 4) & 1) * 8;
    const uint32_t h1b = (uint32_t)__cvta_generic_to_shared(h1t);
    const uint32_t wob = (uint32_t)__cvta_generic_to_shared(WoS);

    float acc2[2][4] = {};
    for (int kt = 0; kt < 4; kt++) {
        for (int i = tid; i < 48 * 64; i += 256) {
            const int r = i >> 6, cc = i & 63;
            WoS[r * SA + cc] = Wo2[(size_t)r * 256 + kt * 64 + cc];
        }
        __syncthreads();
        #pragma unroll
        for (int ks = 0; ks < 4; ks++) {
            uint32_t a[4], b[2][2];
            uint32_t ad = h1b + (uint32_t)(aRow2 * HP + kt * 64 + ks * 16 + aColH) * 2u;
            asm volatile("ldmatrix.sync.aligned.m8n8.x4.shared.b16 {%0,%1,%2,%3}, [%4];\n"
                         : "=r"(a[0]), "=r"(a[1]), "=r"(a[2]), "=r"(a[3]) : "r"(ad));
            uint32_t bd = wob + (uint32_t)((bRow4p * SA) + ks * 16 + bCol4) * 2u;
            asm volatile("ldmatrix.sync.aligned.m8n8.x4.shared.b16 {%0,%1,%2,%3}, [%4];\n"
                         : "=r"(b[0][0]), "=r"(b[0][1]), "=r"(b[1][0]), "=r"(b[1][1])
                         : "r"(bd));
            #pragma unroll
            for (int ni = 0; ni < 2; ni++)
                asm volatile(
                    "mma.sync.aligned.m16n8k16.row.col.f32.f16.f16.f32 "
                    "{%0,%1,%2,%3}, {%4,%5,%6,%7}, {%8,%9}, {%0,%1,%2,%3};\n"
                    : "+f"(acc2[ni][0]), "+f"(acc2[ni][1]),
                      "+f"(acc2[ni][2]), "+f"(acc2[ni][3])
                    : "r"(a[0]), "r"(a[1]), "r"(a[2]), "r"(a[3]),
                      "r"(b[ni][0]), "r"(b[ni][1]));
        }
        __syncthreads();
    }

    #pragma unroll
    for (int ni = 0; ni < 2; ni++) {
        const int m = m0 + warpM2 * 16 + g;
        const int n = warpN2 * 16 + ni * 8 + 2 * l;
        if (n < DOUTc) {
            C[(size_t)m * DOUTc + n]       = acc2[ni][0] + bo[n];
            C[(size_t)(m + 8) * DOUTc + n] = acc2[ni][2] + bo[n];
        }
        if (n + 1 < DOUTc) {
            C[(size_t)m * DOUTc + n + 1]       = acc2[ni][1] + bo[n + 1];
            C[(size_t)(m + 8) * DOUTc + n + 1] = acc2[ni][3] + bo[n + 1];
        }
    }
}

// ---------------------------------------------------------------------------
// Launch
// ---------------------------------------------------------------------------
extern "C" void kernel_launch(void* const* d_in, const int* in_sizes, int n_in,
                              void* d_out, int out_size)
{
    const float* x    = (const float*)d_in[0];
    const int*   idx0 = (const int*)  d_in[1];
    const int*   idx1 = (const int*)  d_in[3];
    const float* Wl0  = (const float*)d_in[5];
    const float* bl0  = (const float*)d_in[6];
    const float* Wr0  = (const float*)d_in[7];
    const float* Wl1  = (const float*)d_in[8];
    const float* bl1  = (const float*)d_in[9];
    const float* Wr1  = (const float*)d_in[10];
    const float* Wo   = (const float*)d_in[11];
    const float* bo   = (const float*)d_in[12];
    float* out = (float*)d_out;

    __half *A0, *W0, *W1, *Wo2, *h0;
    int *list, *remap, *cnt, *mbflag;
    cudaGetSymbolAddress((void**)&A0,     g_A0);
    cudaGetSymbolAddress((void**)&h0,     g_h0);
    cudaGetSymbolAddress((void**)&W0,     g_W0);
    cudaGetSymbolAddress((void**)&W1,     g_W1);
    cudaGetSymbolAddress((void**)&Wo2,    g_Wo2);
    cudaGetSymbolAddress((void**)&list,   g_list);
    cudaGetSymbolAddress((void**)&remap,  g_remap);
    cudaGetSymbolAddress((void**)&cnt,    g_cnt);
    cudaGetSymbolAddress((void**)&mbflag, g_mbflag);

    const int SMEM_F  = 69632;                                // gather buf / W+A union
    const int SMEM_G1 = (32 * 520 + 2 * 256 * 72) * 2;        // 106880 B
    cudaFuncSetAttribute(sage_l0,     cudaFuncAttributeMaxDynamicSharedMemorySize, SMEM_F);
    cudaFuncSetAttribute(gemm1_fused, cudaFuncAttributeMaxDynamicSharedMemorySize, SMEM_G1);

    // Prep: remap/list/cnt/flag init + fp16 weight conversion
    prep_kernel<<<(196608 + 48 * 256 + 255) / 256, 256>>>(
        Wl0, Wr0, Wl1, Wr1, Wo, W0, W1, Wo2, list, remap, cnt, mbflag);

    // Dedup via per-edge CAS claiming
    claim_kernel<<<(E1c + 255) / 256, 256>>>(idx1, list, remap, cnt);

    // FUSED layer 0: full-chip gather then per-CTA GEMM phase (overlapped tail)
    sage_l0<<<444, 256, SMEM_F>>>(x, idx0, list, cnt, A0, W0, bl0, h0, mbflag);

    // Layer 1: integrated aggregation + GEMM + fused projection
    gemm1_fused<<<N2c / 32, 256, SMEM_G1>>>(h0, idx1, remap, W1, bl1, out, Wo2, bo);
}

// round 17
// speedup vs baseline: 1.0374x; 1.0374x over previous
#include <cuda_runtime.h>
#include <cuda_fp16.h>
#include <math.h>
#include <stdint.h>

// Problem geometry (fixed by the dataset)
#define N0c 1048576
#define N1c 65536
#define N2c 4096
#define DEG0c 16
#define DEG1c 10
#define DINc 128
#define DHc 256
#define DOUTc 47
#define E1c (N2c * DEG1c)

// Scratch (alloc-free: __device__ globals)
__device__ __half  g_A0[(size_t)N1c * 256];    // 32 MB  [mean|self] fp16, layer0
__device__ __half  g_h0[(size_t)N1c * 256];    // 32 MB  h0 fp16 (compact rows)
__device__ __half  g_W0[256 * 256];            // [Wl0|Wr0] fp16
__device__ __half  g_W1[256 * 512];            // [Wl1|Wr1] fp16
__device__ __half  g_Wo2[48 * 256];            // Wo fp16, zero-padded to 48 rows
__device__ int     g_list [N1c];               // compact row -> node id
__device__ int     g_remap[N1c];               // node id -> compact row (-1 = unused)
__device__ int     g_cnt;

__device__ __forceinline__ float gelu_exact(float v) {
    return 0.5f * v * (1.0f + erff(v * 0.7071067811865476f));
}

__device__ __forceinline__ void cp16(uint32_t saddr, const void* gaddr) {
    asm volatile("cp.async.cg.shared.global [%0], [%1], 16;\n" :: "r"(saddr), "l"(gaddr));
}

// ---------------------------------------------------------------------------
// prep: remap/list/cnt init (seeds pre-claimed 0..4095) + fp16 weight conv.
// ---------------------------------------------------------------------------
__global__ void prep_kernel(const float* __restrict__ Wl0, const float* __restrict__ Wr0,
                            const float* __restrict__ Wl1, const float* __restrict__ Wr1,
                            const float* __restrict__ Wo,
                            __half* __restrict__ W0, __half* __restrict__ W1,
                            __half* __restrict__ Wo2,
                            int* __restrict__ list, int* __restrict__ remap,
                            int* __restrict__ cnt)
{
    const int t = blockIdx.x * blockDim.x + threadIdx.x;
    if (t < N1c) {
        remap[t] = (t < N2c) ? t : -1;     // seeds claim slots 0..4095
        list[t]  = (t < N2c) ? t : 0;      // padding rows alias node 0
    }
    if (t == 0) *cnt = N2c;
    if (t < 65536) {                       // W0: 256 x 256
        const int n = t >> 8, k = t & 255;
        W0[t] = __float2half_rn(k < 128 ? Wl0[n * 128 + k] : Wr0[n * 128 + (k - 128)]);
    }
    const int t1 = t - 65536;              // W1: 256 x 512
    if (t1 >= 0 && t1 < 131072) {
        const int n = t1 >> 9, k = t1 & 511;
        W1[t1] = __float2half_rn(k < 256 ? Wl1[n * 256 + k] : Wr1[n * 256 + (k - 256)]);
    }
    const int t2 = t - 196608;             // Wo2: 48 x 256 (rows >=47 zero)
    if (t2 >= 0 && t2 < 48 * 256) {
        const int n = t2 >> 8, k = t2 & 255;
        Wo2[t2] = (n < DOUTc) ? __float2half_rn(Wo[n * 256 + k]) : __float2half_rn(0.f);
    }
}

// ---------------------------------------------------------------------------
// claim: per-edge CAS dedup.
// ---------------------------------------------------------------------------
__global__ void claim_kernel(const int* __restrict__ idx1, int* list,
                             int* remap, int* cnt)
{
    const int t = blockIdx.x * blockDim.x + threadIdx.x;
    if (t >= E1c) return;
    const int src = idx1[t];
    if (remap[src] == -1) {
        if (atomicCAS(&remap[src], -1, -2) == -1) {
            const int p = atomicAdd(cnt, 1);
            list[p] = src;
            remap[src] = p;
        }
    }
}

// ---------------------------------------------------------------------------
// Layer-0 operand build (fp32 input): stages DEG neighbor rows + 1 self row
// per dst via cp.async, reduces mean, emits A[dst] = [fp16(mean)|fp16(self)].
// ---------------------------------------------------------------------------
template<int D, int DEG, int NDST>
__global__ void __launch_bounds__(256)
agg_build_kernel(const float* __restrict__ x, const int* __restrict__ idx,
                 __half* __restrict__ A,
                 const int* __restrict__ dlist, const int* __restrict__ cntp)
{
    constexpr int C4   = D / 4;
    constexpr int RPD  = DEG + 1;              // rows per dst (incl. self)
    constexpr int NCHK = NDST * RPD * C4;
    constexpr int PER  = NCHK / 256;
    static_assert(NCHK % 256 == 0, "chunk count");

    const int dst0 = blockIdx.x * NDST;
    const int cnt_pad = (*cntp + NDST - 1) & ~(NDST - 1);
    if (dst0 >= cnt_pad) return;

    extern __shared__ float4 sbuf[];           // [NDST*RPD][C4]
    const uint32_t sbase = (uint32_t)__cvta_generic_to_shared(sbuf);
    const int tid = threadIdx.x;

    #pragma unroll
    for (int p = 0; p < PER; p++) {
        const int c   = tid + p * 256;
        const int eg  = c / C4;
        const int col = c % C4;
        const int dl  = eg / RPD;
        const int e   = eg % RPD;
        const int node = dlist[dst0 + dl];
        const int src = (e < DEG) ? idx[(size_t)node * DEG + e] : node;
        cp16(sbase + (uint32_t)c * 16u, x + (size_t)src * D + col * 4);
    }
    asm volatile("cp.async.commit_group;\n" ::);
    asm volatile("cp.async.wait_group 0;\n" ::);
    __syncthreads();

    constexpr int WPD = 8 / NDST;
    const int warp = tid >> 5, lane = tid & 31;
    const int dl   = warp / WPD;
    const int half = warp % WPD;
    const int col  = half * 32 + lane;         // float4 column, < C4

    float4 acc = make_float4(0.f, 0.f, 0.f, 0.f);
    #pragma unroll
    for (int e = 0; e < DEG; e++) {
        float4 v = sbuf[(dl * RPD + e) * C4 + col];
        acc.x += v.x; acc.y += v.y; acc.z += v.z; acc.w += v.w;
    }
    const float inv = 1.0f / (float)DEG;
    const float4 self = sbuf[(dl * RPD + DEG) * C4 + col];

    __half2* rowm = (__half2*)(A + (size_t)(dst0 + dl) * (2 * D));
    rowm[col * 2]     = __floats2half2_rn(acc.x * inv, acc.y * inv);
    rowm[col * 2 + 1] = __floats2half2_rn(acc.z * inv, acc.w * inv);
    __half2* rows = rowm + D / 2;
    rows[col * 2]     = __floats2half2_rn(self.x, self.y);
    rows[col * 2 + 1] = __floats2half2_rn(self.z, self.w);
}

// ---------------------------------------------------------------------------
// Layer-0 GEMM, persistent W-resident, W QUARTER per CTA (3 CTAs/SM):
// grid = 444 (111 m-owners x 4 col-quarters). (R15 configuration — protected)
// ---------------------------------------------------------------------------
__global__ void __launch_bounds__(256)
sage_gemm0(const __half* __restrict__ A0, const __half* __restrict__ W0,
           const float* __restrict__ bias, __half* __restrict__ h0,
           const int* __restrict__ cntp)
{
    constexpr int WP = 264;            // W smem pitch (halves)
    constexpr int AP = 136;            // A chunk pitch (halves)
    constexpr int WB = 64 * WP;        // W quarter: 64 rows
    constexpr int AB = 64 * AP;        // halves per A buffer

    extern __shared__ __half sm[];
    __half* Ws = sm;                   // [64][WP]
    __half* As = sm + WB;              // [2][64][AP]

    const int tid  = threadIdx.x;
    const int lane = tid & 31;
    const int warp = tid >> 5;
    const int warpM = warp & 1;        // 2 x 32 rows
    const int warpN = warp >> 1;       // 4 x 16 cols
    const int quarter = blockIdx.x & 3;
    const int q0      = blockIdx.x >> 2;   // 0..110
    const int n0 = quarter * 64;

    const int cnt  = *cntp;
    const int n_mb = (cnt + 63) >> 6;

    const uint32_t sW = (uint32_t)__cvta_generic_to_shared(Ws);
    const uint32_t sA = (uint32_t)__cvta_generic_to_shared(As);

    #pragma unroll
    for (int i = 0; i < 8; i++) {
        const int c = tid + i * 256;
        const int r = c >> 5, k16 = c & 31;
        cp16(sW + (uint32_t)(r * WP + k16 * 8) * 2u,
             W0 + (size_t)(n0 + r) * 256 + k16 * 8);
    }

    auto fetchA = [&](int mb, int chunk, int buf) {
        #pragma unroll
        for (int i = 0; i < 4; i++) {
            const int c = tid + i * 256;
            const int r = c >> 4, k16 = c & 15;
            cp16(sA + (uint32_t)(buf * AB + r * AP + k16 * 8) * 2u,
                 A0 + (size_t)(mb * 64 + r) * 256 + chunk * 128 + k16 * 8);
        }
    };

    const int quad = lane >> 3, qr = lane & 7;
    const int aRowB = warpM * 32 + (quad & 1) * 8 + qr;   // + mi*16
    const int aColH = (quad >> 1) * 8;
    const int bRow4 = warpN * 16 + (lane & 7) + ((lane >> 4) & 1) * 8;
    const int bCol4 = ((lane >> 3) & 1) * 8;
    const int g = lane >> 2, l = lane & 3;

    int mb = q0;
    if (mb < n_mb) fetchA(mb, 0, 0);
    asm volatile("cp.async.commit_group;\n" ::);

    for (; mb < n_mb; mb += 111) {
        fetchA(mb, 1, 1);
        asm volatile("cp.async.commit_group;\n" ::);
        asm volatile("cp.async.wait_group 1;\n" ::);
        __syncthreads();

        float acc[2][2][4] = {};

        #pragma unroll
        for (int ks = 0; ks < 8; ks++) {
            uint32_t a[2][4], b[2][2];
            #pragma unroll
            for (int mi = 0; mi < 2; mi++) {
                uint32_t ad = sA + (uint32_t)(((aRowB + mi * 16) * AP) + ks * 16 + aColH) * 2u;
                asm volatile("ldmatrix.sync.aligned.m8n8.x4.shared.b16 {%0,%1,%2,%3}, [%4];\n"
                             : "=r"(a[mi][0]), "=r"(a[mi][1]), "=r"(a[mi][2]), "=r"(a[mi][3])
                             : "r"(ad));
            }
            {
                uint32_t bd = sW + (uint32_t)((bRow4 * WP) + ks * 16 + bCol4) * 2u;
                asm volatile("ldmatrix.sync.aligned.m8n8.x4.shared.b16 {%0,%1,%2,%3}, [%4];\n"
                             : "=r"(b[0][0]), "=r"(b[0][1]), "=r"(b[1][0]), "=r"(b[1][1])
                             : "r"(bd));
            }
            #pragma unroll
            for (int mi = 0; mi < 2; mi++)
                #pragma unroll
                for (int ni = 0; ni < 2; ni++)
                    asm volatile(
                        "mma.sync.aligned.m16n8k16.row.col.f32.f16.f16.f32 "
                        "{%0,%1,%2,%3}, {%4,%5,%6,%7}, {%8,%9}, {%0,%1,%2,%3};\n"
                        : "+f"(acc[mi][ni][0]), "+f"(acc[mi][ni][1]),
                          "+f"(acc[mi][ni][2]), "+f"(acc[mi][ni][3])
                        : "r"(a[mi][0]), "r"(a[mi][1]), "r"(a[mi][2]), "r"(a[mi][3]),
                          "r"(b[ni][0]), "r"(b[ni][1]));
        }
        __syncthreads();

        const int nmb = mb + 111;
        if (nmb < n_mb) fetchA(nmb, 0, 0);
        asm volatile("cp.async.commit_group;\n" ::);
        asm volatile("cp.async.wait_group 1;\n" ::);
        __syncthreads();

        #pragma unroll
        for (int ks = 0; ks < 8; ks++) {
            uint32_t a[2][4], b[2][2];
            #pragma unroll
            for (int mi = 0; mi < 2; mi++) {
                uint32_t ad = sA + (uint32_t)(AB + ((aRowB + mi * 16) * AP) + ks * 16 + aColH) * 2u;
                asm volatile("ldmatrix.sync.aligned.m8n8.x4.shared.b16 {%0,%1,%2,%3}, [%4];\n"
                             : "=r"(a[mi][0]), "=r"(a[mi][1]), "=r"(a[mi][2]), "=r"(a[mi][3])
                             : "r"(ad));
            }
            {
                uint32_t bd = sW + (uint32_t)((bRow4 * WP) + (ks + 8) * 16 + bCol4) * 2u;
                asm volatile("ldmatrix.sync.aligned.m8n8.x4.shared.b16 {%0,%1,%2,%3}, [%4];\n"
                             : "=r"(b[0][0]), "=r"(b[0][1]), "=r"(b[1][0]), "=r"(b[1][1])
                             : "r"(bd));
            }
            #pragma unroll
            for (int mi = 0; mi < 2; mi++)
                #pragma unroll
                for (int ni = 0; ni < 2; ni++)
                    asm volatile(
                        "mma.sync.aligned.m16n8k16.row.col.f32.f16.f16.f32 "
                        "{%0,%1,%2,%3}, {%4,%5,%6,%7}, {%8,%9}, {%0,%1,%2,%3};\n"
                        : "+f"(acc[mi][ni][0]), "+f"(acc[mi][ni][1]),
                          "+f"(acc[mi][ni][2]), "+f"(acc[mi][ni][3])
                        : "r"(a[mi][0]), "r"(a[mi][1]), "r"(a[mi][2]), "r"(a[mi][3]),
                          "r"(b[ni][0]), "r"(b[ni][1]));
        }
        __syncthreads();

        #pragma unroll
        for (int mi = 0; mi < 2; mi++)
            #pragma unroll
            for (int ni = 0; ni < 2; ni++) {
                const int m = mb * 64 + warpM * 32 + mi * 16 + g;
                const int n = n0 + warpN * 16 + ni * 8 + 2 * l;
                float* c = acc[mi][ni];
                *(__half2*)&h0[(size_t)m * 256 + n] =
                    __floats2half2_rn(gelu_exact(c[0] + bias[n]), gelu_exact(c[1] + bias[n + 1]));
                *(__half2*)&h0[(size_t)(m + 8) * 256 + n] =
                    __floats2half2_rn(gelu_exact(c[2] + bias[n]), gelu_exact(c[3] + bias[n + 1]));
            }
    }
}

// ---------------------------------------------------------------------------
// Layer-1 GEMM with INTEGRATED aggregation + fused 47-wide projection.
// NEW: shuffle-parallel index resolution (kills the idx1->srcmap serial
// chain) + 2-deep W pipeline (W[0],W[1] issued before aggregation).
// ---------------------------------------------------------------------------
__global__ void __launch_bounds__(256)
gemm1_fused(const __half* __restrict__ h0, const int* __restrict__ idx1,
            const int* __restrict__ srcmap,
            const __half* __restrict__ W, const float* __restrict__ bias,
            float* __restrict__ C,
            const __half* __restrict__ Wo2, const float* __restrict__ bo)
{
    constexpr int KTOT = 512;
    constexpr int SA = 72;
    constexpr int AP = 520;
    constexpr int AW = 32 * AP;
    constexpr int WW = 256 * SA;

    const int m0 = blockIdx.x * 32;

    extern __shared__ __half sm[];
    __half* As = sm;
    __half* Ws = sm + AW;

    const int tid  = threadIdx.x;
    const int lane = tid & 31;
    const int warp = tid >> 5;
    const int warpM = warp & 1;
    const int warpN = warp >> 1;
    const int arow8 = tid >> 3;
    const int lcolh = (tid & 7) * 8;

    const uint32_t sA = (uint32_t)__cvta_generic_to_shared(As);
    const uint32_t sW = (uint32_t)__cvta_generic_to_shared(Ws);

    auto fetchW = [&](int it, int buf) {
        const int gk = it * 64 + lcolh;
        #pragma unroll
        for (int p = 0; p < 8; p++) {
            const int nr = arow8 + p * 32;
            cp16(sW + (uint32_t)(buf * WW + nr * SA + lcolh) * 2u,
                 W + (size_t)nr * KTOT + gk);
        }
    };

    // 2-deep W prefetch before aggregation (fully hidden under it)
    fetchW(0, 0);
    asm volatile("cp.async.commit_group;\n" ::);
    fetchW(1, 1);
    asm volatile("cp.async.commit_group;\n" ::);

    // ---- integrated aggregation, shuffle-parallel indices ----
    {
        const float inv = 1.0f / (float)DEG1c;
        // Resolve all 40 edge srcs for this warp's 4 dst rows in parallel.
        const int ebase = (m0 + warp * 4) * DEG1c;
        const int s0 = srcmap[idx1[ebase + lane]];
        int s1 = 0;
        if (lane < 8) s1 = srcmap[idx1[ebase + 32 + lane]];

        #pragma unroll
        for (int dl = 0; dl < 4; dl++) {
            const int dst = m0 + warp * 4 + dl;
            float accf[8] = {};
            #pragma unroll
            for (int e = 0; e < DEG1c; e++) {
                const int flat = dl * DEG1c + e;
                const int src = (flat < 32) ? __shfl_sync(0xffffffffu, s0, flat)
                                            : __shfl_sync(0xffffffffu, s1, flat - 32);
                const uint4 v = *(const uint4*)(h0 + (size_t)src * 256 + lane * 8);
                const __half2* hp = (const __half2*)&v;
                #pragma unroll
                for (int j = 0; j < 4; j++) {
                    float2 f = __half22float2(hp[j]);
                    accf[j * 2] += f.x; accf[j * 2 + 1] += f.y;
                }
            }
            const uint4 sv = *(const uint4*)(h0 + (size_t)dst * 256 + lane * 8);
            __half* arow = As + dst % 32 * 0 + (warp * 4 + dl) * AP;
            __half2* mo = (__half2*)(arow + lane * 8);
            mo[0] = __floats2half2_rn(accf[0] * inv, accf[1] * inv);
            mo[1] = __floats2half2_rn(accf[2] * inv, accf[3] * inv);
            mo[2] = __floats2half2_rn(accf[4] * inv, accf[5] * inv);
            mo[3] = __floats2half2_rn(accf[6] * inv, accf[7] * inv);
            *(uint4*)(arow + 256 + lane * 8) = sv;
        }
    }
    __syncthreads();

    float acc[8][4] = {};

    const int quad = lane >> 3, qr = lane & 7;
    const int aRowB = warpM * 16 + (quad & 1) * 8 + qr;
    const int aColH = (quad >> 1) * 8;
    const int bRow4 = warpN * 64 + (lane & 7) + ((lane >> 4) & 1) * 8;
    const int bCol4 = ((lane >> 3) & 1) * 8;

    constexpr int nk = KTOT / 64;
    #pragma unroll 1
    for (int it = 0; it < nk; it++) {
        const int buf = it & 1;
        if (it + 2 < nk) {
            asm volatile("cp.async.wait_group 1;\n" ::);       // W[it] done
        } else {
            asm volatile("cp.async.wait_group 0;\n" ::);
        }
        __syncthreads();

        const uint32_t baseW = sW + (uint32_t)(buf * WW) * 2u;

        #pragma unroll
        for (int ks = 0; ks < 4; ks++) {
            uint32_t a[4], b[8][2];
            uint32_t ad = sA + (uint32_t)((aRowB * AP) + it * 64 + ks * 16 + aColH) * 2u;
            asm volatile("ldmatrix.sync.aligned.m8n8.x4.shared.b16 {%0,%1,%2,%3}, [%4];\n"
                         : "=r"(a[0]), "=r"(a[1]), "=r"(a[2]), "=r"(a[3]) : "r"(ad));
            #pragma unroll
            for (int ni2 = 0; ni2 < 4; ni2++) {
                uint32_t bd = baseW + (uint32_t)(((bRow4 + ni2 * 16) * SA) + ks * 16 + bCol4) * 2u;
                asm volatile("ldmatrix.sync.aligned.m8n8.x4.shared.b16 {%0,%1,%2,%3}, [%4];\n"
                             : "=r"(b[ni2 * 2][0]), "=r"(b[ni2 * 2][1]),
                               "=r"(b[ni2 * 2 + 1][0]), "=r"(b[ni2 * 2 + 1][1])
                             : "r"(bd));
            }
            #pragma unroll
            for (int ni = 0; ni < 8; ni++)
                asm volatile(
                    "mma.sync.aligned.m16n8k16.row.col.f32.f16.f16.f32 "
                    "{%0,%1,%2,%3}, {%4,%5,%6,%7}, {%8,%9}, {%0,%1,%2,%3};\n"
                    : "+f"(acc[ni][0]), "+f"(acc[ni][1]),
                      "+f"(acc[ni][2]), "+f"(acc[ni][3])
                    : "r"(a[0]), "r"(a[1]), "r"(a[2]), "r"(a[3]),
                      "r"(b[ni][0]), "r"(b[ni][1]));
        }
        __syncthreads();
        if (it + 2 < nk) {
            fetchW(it + 2, buf);                               // refill freed buffer
            asm volatile("cp.async.commit_group;\n" ::);
        }
    }

    const int g = lane >> 2, l = lane & 3;

    // ---- fused projection: out[32 x 47] = gelu(h1) @ Wo^T + bo ----
    constexpr int HP = 264;
    __half* h1t = Ws;
    __half* WoS = As;

    __syncthreads();
    #pragma unroll
    for (int ni = 0; ni < 8; ni++) {
        const int ml = warpM * 16 + g;
        const int n  = warpN * 64 + ni * 8 + 2 * l;
        float* c = acc[ni];
        *(__half2*)&h1t[ml * HP + n] =
            __floats2half2_rn(gelu_exact(c[0] + bias[n]), gelu_exact(c[1] + bias[n + 1]));
        *(__half2*)&h1t[(ml + 8) * HP + n] =
            __floats2half2_rn(gelu_exact(c[2] + bias[n]), gelu_exact(c[3] + bias[n + 1]));
    }
    __syncthreads();

    const int warpM2 = warp & 1;
    const int warpN2 = warp >> 1;
    const int aRow2 = warpM2 * 16 + (quad & 1) * 8 + qr;
    const int bRow4p = warpN2 * 16 + (lane & 7) + ((lane >> 4) & 1) * 8;
    const uint32_t h1b = (uint32_t)__cvta_generic_to_shared(h1t);
    const uint32_t wob = (uint32_t)__cvta_generic_to_shared(WoS);

    float acc2[2][4] = {};
    for (int kt = 0; kt < 4; kt++) {
        for (int i = tid; i < 48 * 64; i += 256) {
            const int r = i >> 6, cc = i & 63;
            WoS[r * SA + cc] = Wo2[(size_t)r * 256 + kt * 64 + cc];
        }
        __syncthreads();
        #pragma unroll
        for (int ks = 0; ks < 4; ks++) {
            uint32_t a[4], b[2][2];
            uint32_t ad = h1b + (uint32_t)(aRow2 * HP + kt * 64 + ks * 16 + aColH) * 2u;
            asm volatile("ldmatrix.sync.aligned.m8n8.x4.shared.b16 {%0,%1,%2,%3}, [%4];\n"
                         : "=r"(a[0]), "=r"(a[1]), "=r"(a[2]), "=r"(a[3]) : "r"(ad));
            uint32_t bd = wob + (uint32_t)((bRow4p * SA) + ks * 16 + bCol4) * 2u;
            asm volatile("ldmatrix.sync.aligned.m8n8.x4.shared.b16 {%0,%1,%2,%3}, [%4];\n"
                         : "=r"(b[0][0]), "=r"(b[0][1]), "=r"(b[1][0]), "=r"(b[1][1])
                         : "r"(bd));
            #pragma unroll
            for (int ni = 0; ni < 2; ni++)
                asm volatile(
                    "mma.sync.aligned.m16n8k16.row.col.f32.f16.f16.f32 "
                    "{%0,%1,%2,%3}, {%4,%5,%6,%7}, {%8,%9}, {%0,%1,%2,%3};\n"
                    : "+f"(acc2[ni][0]), "+f"(acc2[ni][1]),
                      "+f"(acc2[ni][2]), "+f"(acc2[ni][3])
                    : "r"(a[0]), "r"(a[1]), "r"(a[2]), "r"(a[3]),
                      "r"(b[ni][0]), "r"(b[ni][1]));
        }
        __syncthreads();
    }

    #pragma unroll
    for (int ni = 0; ni < 2; ni++) {
        const int m = m0 + warpM2 * 16 + g;
        const int n = warpN2 * 16 + ni * 8 + 2 * l;
        if (n < DOUTc) {
            C[(size_t)m * DOUTc + n]       = acc2[ni][0] + bo[n];
            C[(size_t)(m + 8) * DOUTc + n] = acc2[ni][2] + bo[n];
        }
        if (n + 1 < DOUTc) {
            C[(size_t)m * DOUTc + n + 1]       = acc2[ni][1] + bo[n + 1];
            C[(size_t)(m + 8) * DOUTc + n + 1] = acc2[ni][3] + bo[n + 1];
        }
    }
}

// ---------------------------------------------------------------------------
// Launch
// ---------------------------------------------------------------------------
extern "C" void kernel_launch(void* const* d_in, const int* in_sizes, int n_in,
                              void* d_out, int out_size)
{
    const float* x    = (const float*)d_in[0];
    const int*   idx0 = (const int*)  d_in[1];
    const int*   idx1 = (const int*)  d_in[3];
    const float* Wl0  = (const float*)d_in[5];
    const float* bl0  = (const float*)d_in[6];
    const float* Wr0  = (const float*)d_in[7];
    const float* Wl1  = (const float*)d_in[8];
    const float* bl1  = (const float*)d_in[9];
    const float* Wr1  = (const float*)d_in[10];
    const float* Wo   = (const float*)d_in[11];
    const float* bo   = (const float*)d_in[12];
    float* out = (float*)d_out;

    __half *A0, *W0, *W1, *Wo2, *h0;
    int *list, *remap, *cnt;
    cudaGetSymbolAddress((void**)&A0,    g_A0);
    cudaGetSymbolAddress((void**)&h0,    g_h0);
    cudaGetSymbolAddress((void**)&W0,    g_W0);
    cudaGetSymbolAddress((void**)&W1,    g_W1);
    cudaGetSymbolAddress((void**)&Wo2,   g_Wo2);
    cudaGetSymbolAddress((void**)&list,  g_list);
    cudaGetSymbolAddress((void**)&remap, g_remap);
    cudaGetSymbolAddress((void**)&cnt,   g_cnt);

    const int SMEM_S0 = (64 * 264 + 2 * 64 * 136) * 2;        // 68608 B (3 CTAs/SM)
    const int SMEM_G1 = (32 * 520 + 2 * 256 * 72) * 2;        // 106880 B
    const int SMEM_A0 = 8 * (DEG0c + 1) * DINc * 4;           // 69632 B
    cudaFuncSetAttribute(sage_gemm0,  cudaFuncAttributeMaxDynamicSharedMemorySize, SMEM_S0);
    cudaFuncSetAttribute(gemm1_fused, cudaFuncAttributeMaxDynamicSharedMemorySize, SMEM_G1);
    cudaFuncSetAttribute(agg_build_kernel<DINc, DEG0c, 8>,
                         cudaFuncAttributeMaxDynamicSharedMemorySize, SMEM_A0);

    // Prep: seed-claimed remap init + fp16 weight conversion (one launch)
    prep_kernel<<<(196608 + 48 * 256 + 255) / 256, 256>>>(
        Wl0, Wr0, Wl1, Wr1, Wo, W0, W1, Wo2, list, remap, cnt);

    // Dedup via per-edge CAS claiming
    claim_kernel<<<(E1c + 255) / 256, 256>>>(idx1, list, remap, cnt);

    // Layer 0 operand build (compact rows): A0 = [fp16(mean16(x)) | fp16(x_self)]
    agg_build_kernel<DINc, DEG0c, 8>
        <<<N1c / 8, 256, SMEM_A0>>>(x, idx0, A0, list, cnt);

    // Layer 0 GEMM (persistent, W-quarter resident, 3 CTAs/SM): h0 = gelu(A0@W0^T+b)
    sage_gemm0<<<444, 256, SMEM_S0>>>(A0, W0, bl0, h0, cnt);

    // Layer 1: integrated aggregation + GEMM + fused projection
    gemm1_fused<<<N2c / 32, 256, SMEM_G1>>>(h0, idx1, remap, W1, bl1, out, Wo2, bo);
}